// round 10
// baseline (speedup 1.0000x reference)
#include <cuda_runtime.h>
#include <cuda_fp16.h>
#include <cstdint>
#include <math.h>

#define B_   64
#define T_   512
#define D_   512
#define H_   512
#define MTOT (B_ * T_)          // 32768 GEMM rows

// ---------------------------------------------------------------------------
// Scratch (static __device__ — allocation-guard safe)
// ---------------------------------------------------------------------------
// projections in fp16, TRANSPOSED layout: [mat][b][h][t]  (t contiguous)
// + pad so the scan's always-on chunk prefetch can overrun the last row.
__device__ __half g_proj[3][(size_t)B_ * H_ * T_ + 2048];
// fp16 x
__device__ __half g_A[(size_t)MTOT * D_];
// fp16 W^T (stored [N][K] K-major)
__device__ __half g_WT[3][H_ * D_];

// ---------------------------------------------------------------------------
// helpers
// ---------------------------------------------------------------------------
__device__ __forceinline__ uint32_t smem_u32(const void* p) {
    return (uint32_t)__cvta_generic_to_shared(p);
}

__device__ __forceinline__ void cp16(uint32_t dst, const void* src) {
    asm volatile("cp.async.cg.shared.global [%0], [%1], 16;"
                 :: "r"(dst), "l"(src) : "memory");
}
#define CP_COMMIT() asm volatile("cp.async.commit_group;" ::: "memory")
#define CP_WAIT(n)  asm volatile("cp.async.wait_group %0;" :: "n"(n) : "memory")

__device__ __forceinline__ void ldmatrix_x4(uint32_t& r0, uint32_t& r1,
                                            uint32_t& r2, uint32_t& r3,
                                            uint32_t addr) {
    asm volatile("ldmatrix.sync.aligned.m8n8.x4.shared.b16 {%0,%1,%2,%3}, [%4];"
                 : "=r"(r0), "=r"(r1), "=r"(r2), "=r"(r3) : "r"(addr));
}
__device__ __forceinline__ void mma16816(float* c, const uint32_t* a,
                                         const uint32_t* b) {
    asm volatile(
        "mma.sync.aligned.m16n8k16.row.col.f32.f16.f16.f32 "
        "{%0,%1,%2,%3}, {%4,%5,%6,%7}, {%8,%9}, {%0,%1,%2,%3};"
        : "+f"(c[0]), "+f"(c[1]), "+f"(c[2]), "+f"(c[3])
        : "r"(a[0]), "r"(a[1]), "r"(a[2]), "r"(a[3]), "r"(b[0]), "r"(b[1]));
}

// HW tanh (MUFU.TANH, sm_75+)
__device__ __forceinline__ float tanh_hw(float x) {
    float y;
    asm("tanh.approx.f32 %0, %1;" : "=f"(y) : "f"(x));
    return y;
}

__device__ __forceinline__ uint4 ldcs_u4(const uint4* p) {
    uint4 v;
    asm volatile("ld.global.cs.v4.u32 {%0,%1,%2,%3}, [%4];"
                 : "=r"(v.x), "=r"(v.y), "=r"(v.z), "=r"(v.w) : "l"(p));
    return v;
}

// ---------------------------------------------------------------------------
// Kernel 1: convert x to fp16
// ---------------------------------------------------------------------------
__global__ __launch_bounds__(256)
void convert_x_kernel(const float* __restrict__ x) {
    size_t i = (size_t)blockIdx.x * blockDim.x + threadIdx.x;   // one float4
    float4 v = reinterpret_cast<const float4*>(x)[i];
    __half2* Hp = reinterpret_cast<__half2*>(g_A);
    Hp[2 * i]     = __halves2half2(__float2half_rn(v.x), __float2half_rn(v.y));
    Hp[2 * i + 1] = __halves2half2(__float2half_rn(v.z), __float2half_rn(v.w));
}

// ---------------------------------------------------------------------------
// Kernel 2: transpose weights to fp16 [N][K] via 32x33 smem tile
// (coalesced reads AND writes). grid = (16, 16, 3), block = 256.
// ---------------------------------------------------------------------------
__global__ __launch_bounds__(256)
void convert_w_kernel(const float* __restrict__ kz,
                      const float* __restrict__ kr,
                      const float* __restrict__ kh) {
    __shared__ float tile[32][33];
    const float* W = (blockIdx.z == 0) ? kz : (blockIdx.z == 1) ? kr : kh;
    const int k0 = blockIdx.y * 32;
    const int n0 = blockIdx.x * 32;
    const int tx = threadIdx.x & 31;
    const int ty = threadIdx.x >> 5;     // 0..7
    #pragma unroll
    for (int i = 0; i < 4; ++i)
        tile[ty + i * 8][tx] = W[(size_t)(k0 + ty + i * 8) * H_ + n0 + tx];
    __syncthreads();
    #pragma unroll
    for (int i = 0; i < 4; ++i) {
        int n = ty + i * 8;
        g_WT[blockIdx.z][(size_t)(n0 + n) * D_ + k0 + tx] =
            __float2half_rn(tile[tx][n]);
    }
}

// ---------------------------------------------------------------------------
// Kernel 3: fp16 GEMM via mma.sync.m16n8k16.
// CTA tile 128x256, BK=32, 256 threads (8 warps: 2M x 4N, warp tile 64x64).
// 4-stage cp.async pipeline. Epilogue: SMEM transpose (stage memory is dead
// after the loop) -> fully coalesced STG.128 into the [b][h][t] proj layout.
// grid = (6, 256): x = mat*2 + ntile, y = mtile.
// ---------------------------------------------------------------------------
#define A_STAGE   (128 * 80)                 // 10240 B
#define B_STAGE   (256 * 80)                 // 20480 B
#define STAGE_B   (A_STAGE + B_STAGE)        // 30720 B
#define GEMM_SMEM (4 * STAGE_B)              // 122880 B (>= 256*136*2 = 69632)
#define TPAD      136                        // smem transpose row stride (halfs)

__global__ __launch_bounds__(256, 1)
void gemm_kernel() {
    extern __shared__ __align__(128) char dsmem[];
    const uint32_t sbase = smem_u32(dsmem);

    const int tid  = threadIdx.x;
    const int lane = tid & 31;
    const int wid  = tid >> 5;
    const int wm   = (wid & 1) * 64;    // warp M offset in tile
    const int wn   = (wid >> 1) * 64;   // warp N offset in tile

    const int mat   = blockIdx.x >> 1;
    const int nBase = (blockIdx.x & 1) * 256;
    const int mBase = blockIdx.y * 128;

    const __half* Ap = g_A + (size_t)mBase * D_;
    const __half* Wp = g_WT[mat] + (size_t)nBase * D_;

    // loader mapping: rows of 32 halfs = 64B = 4 x 16B chunks
    const int lrow = tid >> 2;       // base row (0..63), stepped by +64
    const int lkc  = tid & 3;        // 16B chunk within row

    // ldmatrix per-lane offsets (row stride 80B; two 8x8 k-halves 16B apart)
    const int a_off = (wm + (lane & 15)) * 80 + (lane >> 4) * 16;
    const int b_off = (wn + (lane & 7) + ((lane >> 4) & 1) * 8) * 80
                    + ((lane >> 3) & 1) * 16;

    float acc[4][8][4];
    #pragma unroll
    for (int i = 0; i < 4; ++i)
        #pragma unroll
        for (int j = 0; j < 8; ++j)
            #pragma unroll
            for (int e = 0; e < 4; ++e) acc[i][j][e] = 0.0f;

    auto load_tile = [&](int j) {                // j = k-tile index 0..15
        const int kk = j * 32;
        const uint32_t sa = sbase + (j & 3) * STAGE_B;
        #pragma unroll
        for (int i = 0; i < 2; ++i) {            // A: 2 chunks per thread
            int row = lrow + i * 64;
            cp16(sa + row * 80 + lkc * 16,
                 Ap + (size_t)row * D_ + kk + lkc * 8);
        }
        #pragma unroll
        for (int i = 0; i < 4; ++i) {            // B: 4 chunks per thread
            int row = lrow + i * 64;
            cp16(sa + A_STAGE + row * 80 + lkc * 16,
                 Wp + (size_t)row * D_ + kk + lkc * 8);
        }
    };

    constexpr int NIT = 16;   // 512 / BK
    load_tile(0);
    CP_COMMIT();
    load_tile(1);
    CP_COMMIT();

    for (int it = 0; it < NIT; ++it) {
        if (it + 2 < NIT) load_tile(it + 2);     // hazard-free (see R4 note)
        CP_COMMIT();
        CP_WAIT(2);
        __syncthreads();

        const uint32_t sa = sbase + (it & 3) * STAGE_B;
        const uint32_t aB = sa + a_off;
        const uint32_t bB = sa + A_STAGE + b_off;

        #pragma unroll
        for (int ks = 0; ks < 2; ++ks) {          // two k16 steps in BK=32
            uint32_t af[4][4], bq[4][4];
            #pragma unroll
            for (int mt = 0; mt < 4; ++mt)
                ldmatrix_x4(af[mt][0], af[mt][1], af[mt][2], af[mt][3],
                            aB + mt * 16 * 80 + ks * 32);
            #pragma unroll
            for (int np = 0; np < 4; ++np)        // each x4 = two n8 b-frags
                ldmatrix_x4(bq[np][0], bq[np][1], bq[np][2], bq[np][3],
                            bB + np * 16 * 80 + ks * 32);
            #pragma unroll
            for (int mt = 0; mt < 4; ++mt)
                #pragma unroll
                for (int nt = 0; nt < 8; ++nt)
                    mma16816(acc[mt][nt], af[mt], &bq[nt >> 1][(nt & 1) * 2]);
        }
    }

    // ---- epilogue: transpose in SMEM, then coalesced stores -------------
    __syncthreads();      // all warps done reading stage buffers
    __half* ts = reinterpret_cast<__half*>(dsmem);   // [256 h][TPAD t]

    const int hl0 = wn + (lane & 3) * 2;    // in-tile h of c0
    const int tl0 = wm + (lane >> 2);       // in-tile t of c0
    #pragma unroll
    for (int mt = 0; mt < 4; ++mt) {
        #pragma unroll
        for (int nt = 0; nt < 8; ++nt) {
            const int hh = hl0 + nt * 8;
            const int tt = tl0 + mt * 16;
            ts[(hh + 0) * TPAD + tt + 0] = __float2half_rn(acc[mt][nt][0]);
            ts[(hh + 1) * TPAD + tt + 0] = __float2half_rn(acc[mt][nt][1]);
            ts[(hh + 0) * TPAD + tt + 8] = __float2half_rn(acc[mt][nt][2]);
            ts[(hh + 1) * TPAD + tt + 8] = __float2half_rn(acc[mt][nt][3]);
        }
    }
    __syncthreads();

    // coalesced: each warp STG.128 covers TWO full 256B h-rows
    const int bq_ = mBase >> 9;          // batch index
    const int tq_ = mBase & 511;         // t offset of this CTA
    __half* Cb = g_proj[mat] + (size_t)bq_ * H_ * T_ + tq_;
    #pragma unroll
    for (int j = 0; j < 16; ++j) {
        const int hl = wid * 32 + j * 2 + (lane >> 4);   // 0..255
        const int tc = (lane & 15) * 8;                   // 0..120
        uint4 v = *reinterpret_cast<const uint4*>(&ts[hl * TPAD + tc]);
        *reinterpret_cast<uint4*>(Cb + (size_t)(nBase + hl) * T_ + tc) = v;
    }
}

// ---------------------------------------------------------------------------
// Kernel 4: diagonal recurrence scan over TRANSPOSED fp16 projections.
// Each lane streams its own contiguous [t] rows with 16B chunks (8 steps
// per LDG -> 8x in-flight bytes per queue slot). 4-chunk prefetch ring
// (32 steps ahead). MUFU.TANH activations. Output stays [b][t][h] fp32.
// ---------------------------------------------------------------------------
__global__ __launch_bounds__(128)
void scan_kernel(const float* __restrict__ h0,
                 const float* __restrict__ mz, const float* __restrict__ mr,
                 const float* __restrict__ bz, const float* __restrict__ br,
                 float* __restrict__ out)
{
    const int gid = blockIdx.x * 128 + threadIdx.x;   // 0 .. B*H-1
    const int b = gid >> 9;
    const int h = gid & 511;

    float hv = h0[(size_t)b * H_ + h];
    const float mzv = mz[h];
    const float mrv = mr[h];
    const float bzv = bz[h];
    const float brv = br[h];

    const size_t rowbase = (size_t)b * H_ * T_ + (size_t)h * T_;   // halfs
    const uint4* xz = reinterpret_cast<const uint4*>(g_proj[0] + rowbase);
    const uint4* xr = reinterpret_cast<const uint4*>(g_proj[1] + rowbase);
    const uint4* xh = reinterpret_cast<const uint4*>(g_proj[2] + rowbase);
    float* o = out + (size_t)b * T_ * H_ + h;

    uint4 rz[4], rr[4], rh[4];
    #pragma unroll
    for (int i = 0; i < 4; ++i) {
        rz[i] = ldcs_u4(xz + i);
        rr[i] = ldcs_u4(xr + i);
        rh[i] = ldcs_u4(xh + i);
    }

    for (int c = 0; c < 64; ++c) {        // 64 chunks x 8 steps = T
        const int slot = c & 3;
        const uint4 uz = rz[slot], ur = rr[slot], uh = rh[slot];

        // prefetch chunk c+4 (overruns into the per-mat pad at the end)
        rz[slot] = ldcs_u4(xz + c + 4);
        rr[slot] = ldcs_u4(xr + c + 4);
        rh[slot] = ldcs_u4(xh + c + 4);

        // unpack 8 halfs of each
        float az[8], ar[8], ah[8];
        {
            const __half2* pz = reinterpret_cast<const __half2*>(&uz);
            const __half2* pr = reinterpret_cast<const __half2*>(&ur);
            const __half2* ph = reinterpret_cast<const __half2*>(&uh);
            #pragma unroll
            for (int q = 0; q < 4; ++q) {
                float2 fz = __half22float2(pz[q]);
                float2 fr = __half22float2(pr[q]);
                float2 fh = __half22float2(ph[q]);
                az[2*q] = fz.x + bzv; az[2*q+1] = fz.y + bzv;
                ar[2*q] = fr.x + brv; ar[2*q+1] = fr.y + brv;
                ah[2*q] = fh.x;       ah[2*q+1] = fh.y;
            }
        }

        float* ob = o + (size_t)(c * 8) * H_;
        #pragma unroll
        for (int i = 0; i < 8; ++i) {
            const float r  = tanh_hw(fmaf(hv, mrv, ar[i])) + 1.0f;
            const float z  = fmaf(0.5f,
                                  tanh_hw(0.5f * fmaf(hv, mzv, az[i])), 0.5f);
            const float ht = tanh_hw(fmaf(r, hv, ah[i]));
            hv = fmaf(z, hv, (1.0f - z) * ht);
            __stcs(ob + (size_t)i * H_, hv);
        }
    }
}

// ---------------------------------------------------------------------------
extern "C" void kernel_launch(void* const* d_in, const int* in_sizes, int n_in,
                              void* d_out, int out_size)
{
    const float* x  = (const float*)d_in[0];
    const float* h0 = (const float*)d_in[1];
    const float* kz = (const float*)d_in[2];
    const float* kr = (const float*)d_in[3];
    const float* kh = (const float*)d_in[4];
    const float* mz = (const float*)d_in[5];
    const float* mr = (const float*)d_in[6];
    const float* bz = (const float*)d_in[7];
    const float* br = (const float*)d_in[8];
    float* out = (float*)d_out;

    cudaFuncSetAttribute(gemm_kernel,
                         cudaFuncAttributeMaxDynamicSharedMemorySize,
                         GEMM_SMEM);

    // convert x to fp16
    convert_x_kernel<<<(MTOT * D_ / 4) / 256, 256>>>(x);
    // transpose weights to fp16 [N][K] (smem-tiled, coalesced both ways)
    convert_w_kernel<<<dim3(16, 16, 3), 256>>>(kz, kr, kh);
    // 3 projections via mma.sync fp16, transposed fp16 output [b][h][t]
    gemm_kernel<<<dim3(6, MTOT / 128), 256, GEMM_SMEM>>>();
    // recurrence
    scan_kernel<<<(B_ * H_) / 128, 128>>>(h0, mz, mr, bz, br, out);
}

// round 11
// speedup vs baseline: 1.3125x; 1.3125x over previous
#include <cuda_runtime.h>
#include <cuda_fp16.h>
#include <cstdint>
#include <math.h>

#define B_   64
#define T_   512
#define D_   512
#define H_   512
#define MTOT (B_ * T_)          // 32768 GEMM rows

// ---------------------------------------------------------------------------
// Scratch (static __device__ — allocation-guard safe)
// ---------------------------------------------------------------------------
// projections xz, xr, xh in fp16, layout [b*t][h] (+32-step pad for the
// scan prefetch ring).
__device__ __half g_proj[3][(size_t)MTOT * H_ + 32 * H_];
// fp16 W^T (stored [N][K] K-major)
__device__ __half g_WT[3][H_ * D_];

// ---------------------------------------------------------------------------
// helpers
// ---------------------------------------------------------------------------
__device__ __forceinline__ uint32_t smem_u32(const void* p) {
    return (uint32_t)__cvta_generic_to_shared(p);
}

__device__ __forceinline__ void cp16(uint32_t dst, const void* src) {
    asm volatile("cp.async.cg.shared.global [%0], [%1], 16;"
                 :: "r"(dst), "l"(src) : "memory");
}
#define CP_COMMIT() asm volatile("cp.async.commit_group;" ::: "memory")
#define CP_WAIT(n)  asm volatile("cp.async.wait_group %0;" :: "n"(n) : "memory")

__device__ __forceinline__ void ldmatrix_x4(uint32_t& r0, uint32_t& r1,
                                            uint32_t& r2, uint32_t& r3,
                                            uint32_t addr) {
    asm volatile("ldmatrix.sync.aligned.m8n8.x4.shared.b16 {%0,%1,%2,%3}, [%4];"
                 : "=r"(r0), "=r"(r1), "=r"(r2), "=r"(r3) : "r"(addr));
}
__device__ __forceinline__ void mma16816(float* c, const uint32_t* a,
                                         const uint32_t* b) {
    asm volatile(
        "mma.sync.aligned.m16n8k16.row.col.f32.f16.f16.f32 "
        "{%0,%1,%2,%3}, {%4,%5,%6,%7}, {%8,%9}, {%0,%1,%2,%3};"
        : "+f"(c[0]), "+f"(c[1]), "+f"(c[2]), "+f"(c[3])
        : "r"(a[0]), "r"(a[1]), "r"(a[2]), "r"(a[3]), "r"(b[0]), "r"(b[1]));
}

// HW tanh (MUFU.TANH, sm_75+)
__device__ __forceinline__ float tanh_hw(float x) {
    float y;
    asm("tanh.approx.f32 %0, %1;" : "=f"(y) : "f"(x));
    return y;
}

// streaming 2-byte load -> fp32
__device__ __forceinline__ float ldcs_h2f(const __half* p) {
    unsigned short u = __ldcs(reinterpret_cast<const unsigned short*>(p));
    return __half2float(__ushort_as_half(u));
}

// 8-byte shared store of two half2
__device__ __forceinline__ void sts8(uint32_t addr, __half2 a, __half2 b) {
    uint32_t ua = *reinterpret_cast<uint32_t*>(&a);
    uint32_t ub = *reinterpret_cast<uint32_t*>(&b);
    asm volatile("st.shared.v2.b32 [%0], {%1, %2};"
                 :: "r"(addr), "r"(ua), "r"(ub) : "memory");
}

// ---------------------------------------------------------------------------
// Kernel 1: transpose weights to fp16 [N][K] via 32x33 smem tile
// (coalesced reads AND writes). grid = (16, 16, 3), block = 256.
// ---------------------------------------------------------------------------
__global__ __launch_bounds__(256)
void convert_w_kernel(const float* __restrict__ kz,
                      const float* __restrict__ kr,
                      const float* __restrict__ kh) {
    __shared__ float tile[32][33];
    const float* W = (blockIdx.z == 0) ? kz : (blockIdx.z == 1) ? kr : kh;
    const int k0 = blockIdx.y * 32;
    const int n0 = blockIdx.x * 32;
    const int tx = threadIdx.x & 31;
    const int ty = threadIdx.x >> 5;     // 0..7
    #pragma unroll
    for (int i = 0; i < 4; ++i)
        tile[ty + i * 8][tx] = W[(size_t)(k0 + ty + i * 8) * H_ + n0 + tx];
    __syncthreads();
    #pragma unroll
    for (int i = 0; i < 4; ++i) {
        int n = ty + i * 8;
        g_WT[blockIdx.z][(size_t)(n0 + n) * D_ + k0 + tx] =
            __float2half_rn(tile[tx][n]);
    }
}

// ---------------------------------------------------------------------------
// Kernel 2: fp16 GEMM via mma.sync.m16n8k16, FUSED x fp32->fp16 conversion
// in the A-loader (no g_A pass). CTA tile 128x256, BK=32, 256 threads
// (8 warps: 2M x 4N, warp tile 64x64). B: 4-stage cp.async pipeline;
// A: fp32 LDG.128 held one iteration in regs, then cvt + STS.64.
// SMEM rows padded to 80B -> conflict-free. Epilogue packs fp16 half2.
// grid = (6, 256): x = mat*2 + ntile, y = mtile.
// ---------------------------------------------------------------------------
#define A_STAGE   (128 * 80)                 // 10240 B
#define B_STAGE   (256 * 80)                 // 20480 B
#define STAGE_B   (A_STAGE + B_STAGE)        // 30720 B
#define GEMM_SMEM (4 * STAGE_B)              // 122880 B

__global__ __launch_bounds__(256, 1)
void gemm_kernel(const float* __restrict__ x) {
    extern __shared__ __align__(128) char dsmem[];
    const uint32_t sbase = smem_u32(dsmem);

    const int tid  = threadIdx.x;
    const int lane = tid & 31;
    const int wid  = tid >> 5;
    const int wm   = (wid & 1) * 64;    // warp M offset in tile
    const int wn   = (wid >> 1) * 64;   // warp N offset in tile

    const int mat   = blockIdx.x >> 1;
    const int nBase = (blockIdx.x & 1) * 256;
    const int mBase = blockIdx.y * 128;

    const float* Xb  = x + (size_t)mBase * D_;
    const __half* Wp = g_WT[mat] + (size_t)nBase * D_;
    __half* C = g_proj[mat];

    // ---- A loader (fp32 -> fp16): 1024 16B-fp32-chunks/stage, 4/thread.
    // chunk c: row = c>>3 (0..127), kc = c&7 (16B fp32 = 4 floats)
    int arow[4], akc[4];
    uint32_t asts[4];                    // smem offset within stage
    #pragma unroll
    for (int i = 0; i < 4; ++i) {
        int c = tid + i * 256;
        arow[i] = c >> 3;
        akc[i]  = c & 7;
        asts[i] = (uint32_t)(arow[i] * 80 + akc[i] * 8);
    }
    float4 a4[4];                        // held fp32 chunks (one stage)

    auto ldg_a = [&](int j) {            // issue LDG for stage j
        const int kk = j * 32;
        #pragma unroll
        for (int i = 0; i < 4; ++i)
            a4[i] = __ldg(reinterpret_cast<const float4*>(
                        Xb + (size_t)arow[i] * D_ + kk + akc[i] * 4));
    };
    auto sts_a = [&](int j) {            // convert + store held chunks
        const uint32_t sa = sbase + (j & 3) * STAGE_B;
        #pragma unroll
        for (int i = 0; i < 4; ++i)
            sts8(sa + asts[i],
                 __floats2half2_rn(a4[i].x, a4[i].y),
                 __floats2half2_rn(a4[i].z, a4[i].w));
    };

    // ---- B loader: cp.async, 4 chunks/thread
    const int lrow = tid >> 2;
    const int lkc  = tid & 3;
    auto load_b = [&](int j) {
        const int kk = j * 32;
        const uint32_t sb = sbase + (j & 3) * STAGE_B + A_STAGE;
        #pragma unroll
        for (int i = 0; i < 4; ++i) {
            int row = lrow + i * 64;
            cp16(sb + row * 80 + lkc * 16,
                 Wp + (size_t)row * D_ + kk + lkc * 8);
        }
    };

    // ldmatrix per-lane offsets (row stride 80B; two 8x8 k-halves 16B apart)
    const int a_off = (wm + (lane & 15)) * 80 + (lane >> 4) * 16;
    const int b_off = (wn + (lane & 7) + ((lane >> 4) & 1) * 8) * 80
                    + ((lane >> 3) & 1) * 16;

    float acc[4][8][4];
    #pragma unroll
    for (int i = 0; i < 4; ++i)
        #pragma unroll
        for (int j = 0; j < 8; ++j)
            #pragma unroll
            for (int e = 0; e < 4; ++e) acc[i][j][e] = 0.0f;

    constexpr int NIT = 16;   // 512 / BK
    // prologue: A(0) loaded+stored (latency exposed once), A(1) held in regs
    ldg_a(0); sts_a(0);
    ldg_a(1);
    load_b(0); CP_COMMIT();
    load_b(1); CP_COMMIT();

    for (int it = 0; it < NIT; ++it) {
        // A: store stage it+1 from held regs, then refill regs for it+2.
        // STS target buffer (it+1)&3 was last read at it-3 -> safe.
        if (it + 1 < NIT) sts_a(it + 1);
        if (it + 2 < NIT) ldg_a(it + 2);
        // B: prefetch stage it+2 (buffer last read at it-2 -> safe)
        if (it + 2 < NIT) load_b(it + 2);
        CP_COMMIT();               // empty commits at tail keep wait math uniform
        CP_WAIT(2);                // B of stage it resident
        __syncthreads();           // + A STS of stage it (done at it-1) visible

        const uint32_t sa = sbase + (it & 3) * STAGE_B;
        const uint32_t aB = sa + a_off;
        const uint32_t bB = sa + A_STAGE + b_off;

        #pragma unroll
        for (int ks = 0; ks < 2; ++ks) {          // two k16 steps in BK=32
            uint32_t af[4][4], bq[4][4];
            #pragma unroll
            for (int mt = 0; mt < 4; ++mt)
                ldmatrix_x4(af[mt][0], af[mt][1], af[mt][2], af[mt][3],
                            aB + mt * 16 * 80 + ks * 32);
            #pragma unroll
            for (int np = 0; np < 4; ++np)        // each x4 = two n8 b-frags
                ldmatrix_x4(bq[np][0], bq[np][1], bq[np][2], bq[np][3],
                            bB + np * 16 * 80 + ks * 32);
            #pragma unroll
            for (int mt = 0; mt < 4; ++mt)
                #pragma unroll
                for (int nt = 0; nt < 8; ++nt)
                    mma16816(acc[mt][nt], af[mt], &bq[nt >> 1][(nt & 1) * 2]);
        }
    }

    // epilogue: pack adjacent col pairs to half2 (4B stores)
    const int row0 = mBase + wm + (lane >> 2);
    const int col0 = nBase + wn + (lane & 3) * 2;
    #pragma unroll
    for (int mt = 0; mt < 4; ++mt) {
        #pragma unroll
        for (int nt = 0; nt < 8; ++nt) {
            __half* p = C + (size_t)(row0 + mt * 16) * H_ + col0 + nt * 8;
            *reinterpret_cast<__half2*>(p) =
                __floats2half2_rn(acc[mt][nt][0], acc[mt][nt][1]);
            *reinterpret_cast<__half2*>(p + 8 * H_) =
                __floats2half2_rn(acc[mt][nt][2], acc[mt][nt][3]);
        }
    }
}

// ---------------------------------------------------------------------------
// Kernel 3: diagonal recurrence scan (R9 version — measured best).
// One lane/thread, h-coalesced 2B loads, depth-32 prefetch ring
// (6.3 MB in flight), MUFU.TANH activations.
// ---------------------------------------------------------------------------
__global__ __launch_bounds__(128)
void scan_kernel(const float* __restrict__ h0,
                 const float* __restrict__ mz, const float* __restrict__ mr,
                 const float* __restrict__ bz, const float* __restrict__ br,
                 float* __restrict__ out)
{
    const int gid = blockIdx.x * 128 + threadIdx.x;   // 0 .. B*H-1
    const int b = gid >> 9;
    const int h = gid & 511;

    float hv = h0[gid];
    const float mzv = mz[h];
    const float mrv = mr[h];
    const float bzv = bz[h];
    const float brv = br[h];

    const size_t base = (size_t)b * T_ * H_ + h;
    const __half* xz = g_proj[0] + base;
    const __half* xr = g_proj[1] + base;
    const __half* xh = g_proj[2] + base;
    float* o = out + base;

    float vz[32], vr[32], vh[32];
    #pragma unroll
    for (int i = 0; i < 32; ++i) {
        size_t off = (size_t)i * H_;
        vz[i] = ldcs_h2f(xz + off);
        vr[i] = ldcs_h2f(xr + off);
        vh[i] = ldcs_h2f(xh + off);
    }

    for (int t0 = 0; t0 < T_; t0 += 32) {
        #pragma unroll
        for (int i = 0; i < 32; ++i) {
            const float az = vz[i] + bzv;
            const float ar = vr[i] + brv;
            const float ah = vh[i];

            // prefetch t0+i+32 (lands in the padded tail on the last block)
            const size_t poff = (size_t)(t0 + i + 32) * H_;
            vz[i] = ldcs_h2f(xz + poff);
            vr[i] = ldcs_h2f(xr + poff);
            vh[i] = ldcs_h2f(xh + poff);

            const float r  = tanh_hw(fmaf(hv, mrv, ar)) + 1.0f;
            const float z  = fmaf(0.5f,
                                  tanh_hw(0.5f * fmaf(hv, mzv, az)), 0.5f);
            const float ht = tanh_hw(fmaf(r, hv, ah));
            hv = fmaf(z, hv, (1.0f - z) * ht);

            __stcs(o + (size_t)(t0 + i) * H_, hv);
        }
    }
}

// ---------------------------------------------------------------------------
extern "C" void kernel_launch(void* const* d_in, const int* in_sizes, int n_in,
                              void* d_out, int out_size)
{
    const float* x  = (const float*)d_in[0];
    const float* h0 = (const float*)d_in[1];
    const float* kz = (const float*)d_in[2];
    const float* kr = (const float*)d_in[3];
    const float* kh = (const float*)d_in[4];
    const float* mz = (const float*)d_in[5];
    const float* mr = (const float*)d_in[6];
    const float* bz = (const float*)d_in[7];
    const float* br = (const float*)d_in[8];
    float* out = (float*)d_out;

    cudaFuncSetAttribute(gemm_kernel,
                         cudaFuncAttributeMaxDynamicSharedMemorySize,
                         GEMM_SMEM);

    // transpose weights to fp16 [N][K] (smem-tiled, coalesced both ways)
    convert_w_kernel<<<dim3(16, 16, 3), 256>>>(kz, kr, kh);
    // 3 projections via mma.sync fp16 (x converted in-loader), fp16 output
    gemm_kernel<<<dim3(6, MTOT / 128), 256, GEMM_SMEM>>>(x);
    // recurrence
    scan_kernel<<<(B_ * H_) / 128, 128>>>(h0, mz, mr, bz, br, out);
}

// round 12
// speedup vs baseline: 1.3663x; 1.0410x over previous
#include <cuda_runtime.h>
#include <cuda_fp16.h>
#include <cstdint>
#include <math.h>

#define B_   64
#define T_   512
#define D_   512
#define H_   512
#define MTOT (B_ * T_)          // 32768 GEMM rows

// ---------------------------------------------------------------------------
// Scratch (static __device__ — allocation-guard safe)
// ---------------------------------------------------------------------------
// projections xz, xr, xh in fp16, layout [b*t][h] (+64-step pad: the scan's
// cp.async pipeline prefetches up to 3 stages = 48 steps past the end).
__device__ __half g_proj[3][(size_t)MTOT * H_ + 64 * H_];
// fp16 W^T (stored [N][K] K-major)
__device__ __half g_WT[3][H_ * D_];

// ---------------------------------------------------------------------------
// helpers
// ---------------------------------------------------------------------------
__device__ __forceinline__ uint32_t smem_u32(const void* p) {
    return (uint32_t)__cvta_generic_to_shared(p);
}

__device__ __forceinline__ void cp16(uint32_t dst, const void* src) {
    asm volatile("cp.async.cg.shared.global [%0], [%1], 16;"
                 :: "r"(dst), "l"(src) : "memory");
}
#define CP_COMMIT() asm volatile("cp.async.commit_group;" ::: "memory")
#define CP_WAIT(n)  asm volatile("cp.async.wait_group %0;" :: "n"(n) : "memory")

__device__ __forceinline__ void ldmatrix_x4(uint32_t& r0, uint32_t& r1,
                                            uint32_t& r2, uint32_t& r3,
                                            uint32_t addr) {
    asm volatile("ldmatrix.sync.aligned.m8n8.x4.shared.b16 {%0,%1,%2,%3}, [%4];"
                 : "=r"(r0), "=r"(r1), "=r"(r2), "=r"(r3) : "r"(addr));
}
__device__ __forceinline__ void mma16816(float* c, const uint32_t* a,
                                         const uint32_t* b) {
    asm volatile(
        "mma.sync.aligned.m16n8k16.row.col.f32.f16.f16.f32 "
        "{%0,%1,%2,%3}, {%4,%5,%6,%7}, {%8,%9}, {%0,%1,%2,%3};"
        : "+f"(c[0]), "+f"(c[1]), "+f"(c[2]), "+f"(c[3])
        : "r"(a[0]), "r"(a[1]), "r"(a[2]), "r"(a[3]), "r"(b[0]), "r"(b[1]));
}

// HW tanh (MUFU.TANH, sm_75+)
__device__ __forceinline__ float tanh_hw(float x) {
    float y;
    asm("tanh.approx.f32 %0, %1;" : "=f"(y) : "f"(x));
    return y;
}

// 8-byte shared store of two half2
__device__ __forceinline__ void sts8(uint32_t addr, __half2 a, __half2 b) {
    uint32_t ua = *reinterpret_cast<uint32_t*>(&a);
    uint32_t ub = *reinterpret_cast<uint32_t*>(&b);
    asm volatile("st.shared.v2.b32 [%0], {%1, %2};"
                 :: "r"(addr), "r"(ua), "r"(ub) : "memory");
}

// ---------------------------------------------------------------------------
// Kernel 1: transpose weights to fp16 [N][K] via 32x33 smem tile
// (coalesced reads AND writes). grid = (16, 16, 3), block = 256.
// ---------------------------------------------------------------------------
__global__ __launch_bounds__(256)
void convert_w_kernel(const float* __restrict__ kz,
                      const float* __restrict__ kr,
                      const float* __restrict__ kh) {
    __shared__ float tile[32][33];
    const float* W = (blockIdx.z == 0) ? kz : (blockIdx.z == 1) ? kr : kh;
    const int k0 = blockIdx.y * 32;
    const int n0 = blockIdx.x * 32;
    const int tx = threadIdx.x & 31;
    const int ty = threadIdx.x >> 5;     // 0..7
    #pragma unroll
    for (int i = 0; i < 4; ++i)
        tile[ty + i * 8][tx] = W[(size_t)(k0 + ty + i * 8) * H_ + n0 + tx];
    __syncthreads();
    #pragma unroll
    for (int i = 0; i < 4; ++i) {
        int n = ty + i * 8;
        g_WT[blockIdx.z][(size_t)(n0 + n) * D_ + k0 + tx] =
            __float2half_rn(tile[tx][n]);
    }
}

// ---------------------------------------------------------------------------
// Kernel 2: fp16 GEMM via mma.sync.m16n8k16, FUSED x fp32->fp16 conversion
// in the A-loader. CTA tile 128x256, BK=32, 256 threads (8 warps: 2M x 4N,
// warp tile 64x64). B: 4-stage cp.async pipeline; A: fp32 LDG.128 held one
// iteration in regs, then cvt + STS.64. 80B smem rows -> conflict-free.
// grid = (6, 256): x = mat*2 + ntile, y = mtile.   (unchanged from R11)
// ---------------------------------------------------------------------------
#define A_STAGE   (128 * 80)                 // 10240 B
#define B_STAGE   (256 * 80)                 // 20480 B
#define STAGE_B   (A_STAGE + B_STAGE)        // 30720 B
#define GEMM_SMEM (4 * STAGE_B)              // 122880 B

__global__ __launch_bounds__(256, 1)
void gemm_kernel(const float* __restrict__ x) {
    extern __shared__ __align__(128) char dsmem[];
    const uint32_t sbase = smem_u32(dsmem);

    const int tid  = threadIdx.x;
    const int lane = tid & 31;
    const int wid  = tid >> 5;
    const int wm   = (wid & 1) * 64;    // warp M offset in tile
    const int wn   = (wid >> 1) * 64;   // warp N offset in tile

    const int mat   = blockIdx.x >> 1;
    const int nBase = (blockIdx.x & 1) * 256;
    const int mBase = blockIdx.y * 128;

    const float* Xb  = x + (size_t)mBase * D_;
    const __half* Wp = g_WT[mat] + (size_t)nBase * D_;
    __half* C = g_proj[mat];

    // ---- A loader (fp32 -> fp16): 1024 16B-fp32-chunks/stage, 4/thread.
    int arow[4], akc[4];
    uint32_t asts[4];
    #pragma unroll
    for (int i = 0; i < 4; ++i) {
        int c = tid + i * 256;
        arow[i] = c >> 3;
        akc[i]  = c & 7;
        asts[i] = (uint32_t)(arow[i] * 80 + akc[i] * 8);
    }
    float4 a4[4];

    auto ldg_a = [&](int j) {
        const int kk = j * 32;
        #pragma unroll
        for (int i = 0; i < 4; ++i)
            a4[i] = __ldg(reinterpret_cast<const float4*>(
                        Xb + (size_t)arow[i] * D_ + kk + akc[i] * 4));
    };
    auto sts_a = [&](int j) {
        const uint32_t sa = sbase + (j & 3) * STAGE_B;
        #pragma unroll
        for (int i = 0; i < 4; ++i)
            sts8(sa + asts[i],
                 __floats2half2_rn(a4[i].x, a4[i].y),
                 __floats2half2_rn(a4[i].z, a4[i].w));
    };

    // ---- B loader: cp.async, 4 chunks/thread
    const int lrow = tid >> 2;
    const int lkc  = tid & 3;
    auto load_b = [&](int j) {
        const int kk = j * 32;
        const uint32_t sb = sbase + (j & 3) * STAGE_B + A_STAGE;
        #pragma unroll
        for (int i = 0; i < 4; ++i) {
            int row = lrow + i * 64;
            cp16(sb + row * 80 + lkc * 16,
                 Wp + (size_t)row * D_ + kk + lkc * 8);
        }
    };

    const int a_off = (wm + (lane & 15)) * 80 + (lane >> 4) * 16;
    const int b_off = (wn + (lane & 7) + ((lane >> 4) & 1) * 8) * 80
                    + ((lane >> 3) & 1) * 16;

    float acc[4][8][4];
    #pragma unroll
    for (int i = 0; i < 4; ++i)
        #pragma unroll
        for (int j = 0; j < 8; ++j)
            #pragma unroll
            for (int e = 0; e < 4; ++e) acc[i][j][e] = 0.0f;

    constexpr int NIT = 16;
    ldg_a(0); sts_a(0);
    ldg_a(1);
    load_b(0); CP_COMMIT();
    load_b(1); CP_COMMIT();

    for (int it = 0; it < NIT; ++it) {
        if (it + 1 < NIT) sts_a(it + 1);       // buffer (it+1)&3: safe
        if (it + 2 < NIT) ldg_a(it + 2);
        if (it + 2 < NIT) load_b(it + 2);      // buffer (it+2)&3: safe
        CP_COMMIT();
        CP_WAIT(2);
        __syncthreads();

        const uint32_t sa = sbase + (it & 3) * STAGE_B;
        const uint32_t aB = sa + a_off;
        const uint32_t bB = sa + A_STAGE + b_off;

        #pragma unroll
        for (int ks = 0; ks < 2; ++ks) {
            uint32_t af[4][4], bq[4][4];
            #pragma unroll
            for (int mt = 0; mt < 4; ++mt)
                ldmatrix_x4(af[mt][0], af[mt][1], af[mt][2], af[mt][3],
                            aB + mt * 16 * 80 + ks * 32);
            #pragma unroll
            for (int np = 0; np < 4; ++np)
                ldmatrix_x4(bq[np][0], bq[np][1], bq[np][2], bq[np][3],
                            bB + np * 16 * 80 + ks * 32);
            #pragma unroll
            for (int mt = 0; mt < 4; ++mt)
                #pragma unroll
                for (int nt = 0; nt < 8; ++nt)
                    mma16816(acc[mt][nt], af[mt], &bq[nt >> 1][(nt & 1) * 2]);
        }
    }

    const int row0 = mBase + wm + (lane >> 2);
    const int col0 = nBase + wn + (lane & 3) * 2;
    #pragma unroll
    for (int mt = 0; mt < 4; ++mt) {
        #pragma unroll
        for (int nt = 0; nt < 8; ++nt) {
            __half* p = C + (size_t)(row0 + mt * 16) * H_ + col0 + nt * 8;
            *reinterpret_cast<__half2*>(p) =
                __floats2half2_rn(acc[mt][nt][0], acc[mt][nt][1]);
            *reinterpret_cast<__half2*>(p + 8 * H_) =
                __floats2half2_rn(acc[mt][nt][2], acc[mt][nt][3]);
        }
    }
}

// ---------------------------------------------------------------------------
// Kernel 3: diagonal recurrence scan, cp.async-staged.
// The register-ring version is capped by the per-warp LDG scoreboard
// (~55 outstanding loads -> 3.6 MB in flight chip-wide). cp.async has no
// such cap and holds no registers: each 128-thread block owns 128 h-lanes
// and streams 3 x [16 t x 128 h] fp16 stages (12 KB) through a 4-deep
// SMEM pipeline (~9 MB in flight chip-wide). Per step: 3 conflict-free
// 2B LDS per thread. MUFU.TANH activations. Values bit-identical to R9.
// ---------------------------------------------------------------------------
#define SC_STAGE 12288                     // 3 mats * 16 t * 256 B
#define SC_SMEM  (4 * SC_STAGE)            // 49152 B

__global__ __launch_bounds__(128)
void scan_kernel(const float* __restrict__ h0,
                 const float* __restrict__ mz, const float* __restrict__ mr,
                 const float* __restrict__ bz, const float* __restrict__ br,
                 float* __restrict__ out)
{
    extern __shared__ __align__(16) char ssm[];
    const uint32_t sb = smem_u32(ssm);
    const int tid = threadIdx.x;
    const int b   = blockIdx.x >> 2;        // 4 blocks per batch
    const int hb  = blockIdx.x & 3;
    const int h   = hb * 128 + tid;

    float hv = h0[(size_t)b * H_ + h];
    const float mzv = mz[h];
    const float mrv = mr[h];
    const float bzv = bz[h];
    const float brv = br[h];

    // base (in halfs) of this block's h-segment at t=0
    const size_t rowb = (size_t)b * T_ * H_ + (size_t)hb * 128;

    // loader: 768 16B-chunks per stage, 6 per thread
    auto load_stage = [&](int s) {          // s = t-chunk index (16 steps)
        const uint32_t dst = sb + (s & 3) * SC_STAGE;
        #pragma unroll
        for (int j = 0; j < 6; ++j) {
            const int ch  = tid + j * 128;
            const int mat = ch >> 8;              // 0..2
            const int tt  = (ch >> 4) & 15;       // 0..15
            const int seg = ch & 15;              // 0..15 (8 halfs each)
            const __half* src = g_proj[mat] + rowb
                              + (size_t)(s * 16 + tt) * H_ + seg * 8;
            cp16(dst + mat * 4096 + tt * 256 + seg * 16, src);
        }
    };

    load_stage(0); CP_COMMIT();
    load_stage(1); CP_COMMIT();
    load_stage(2); CP_COMMIT();

    float* o = out + (size_t)b * T_ * H_ + h;
    const __half* sm = reinterpret_cast<const __half*>(ssm);

    for (int c = 0; c < 32; ++c) {          // 32 chunks x 16 steps = T
        CP_WAIT(2);                          // stage c resident (this thread)
        __syncthreads();                     // ...and all threads' chunks

        // prefetch stage c+3 into buffer (c-1)&3 — its compute finished
        // before the sync above. Overrun (s up to 34) lands in the 64-step
        // pad of g_proj.
        load_stage(c + 3);
        CP_COMMIT();

        const int sbuf = (c & 3) * (SC_STAGE / 2);   // offset in halfs
        float* ob = o + (size_t)(c * 16) * H_;
        #pragma unroll
        for (int i = 0; i < 16; ++i) {
            const int so = sbuf + i * 128 + tid;     // halfs (256B rows)
            const float az = __half2float(sm[so])          + bzv;
            const float ar = __half2float(sm[so + 2048])   + brv;
            const float ah = __half2float(sm[so + 4096]);

            const float r  = tanh_hw(fmaf(hv, mrv, ar)) + 1.0f;
            const float z  = fmaf(0.5f,
                                  tanh_hw(0.5f * fmaf(hv, mzv, az)), 0.5f);
            const float ht = tanh_hw(fmaf(r, hv, ah));
            hv = fmaf(z, hv, (1.0f - z) * ht);

            __stcs(ob + (size_t)i * H_, hv);
        }
    }
}

// ---------------------------------------------------------------------------
extern "C" void kernel_launch(void* const* d_in, const int* in_sizes, int n_in,
                              void* d_out, int out_size)
{
    const float* x  = (const float*)d_in[0];
    const float* h0 = (const float*)d_in[1];
    const float* kz = (const float*)d_in[2];
    const float* kr = (const float*)d_in[3];
    const float* kh = (const float*)d_in[4];
    const float* mz = (const float*)d_in[5];
    const float* mr = (const float*)d_in[6];
    const float* bz = (const float*)d_in[7];
    const float* br = (const float*)d_in[8];
    float* out = (float*)d_out;

    cudaFuncSetAttribute(gemm_kernel,
                         cudaFuncAttributeMaxDynamicSharedMemorySize,
                         GEMM_SMEM);
    cudaFuncSetAttribute(scan_kernel,
                         cudaFuncAttributeMaxDynamicSharedMemorySize,
                         SC_SMEM);

    // transpose weights to fp16 [N][K]
    convert_w_kernel<<<dim3(16, 16, 3), 256>>>(kz, kr, kh);
    // 3 projections via mma.sync fp16 (x converted in-loader), fp16 output
    gemm_kernel<<<dim3(6, MTOT / 128), 256, GEMM_SMEM>>>(x);
    // recurrence (cp.async-staged)
    scan_kernel<<<(B_ * H_) / 128, 128, SC_SMEM>>>(h0, mz, mr, bz, br, out);
}